// round 10
// baseline (speedup 1.0000x reference)
#include <cuda_runtime.h>
#include <cuda_fp16.h>
#include <math_constants.h>
#include <cstdint>

#define Nn 64
#define Ll 1024
#define Hh 1024

// ---------------------------------------------------------------------------
// Device scratch
// ---------------------------------------------------------------------------
__device__ float g_dhP[4][Nn * Hh];
__device__ float g_scoreP[8][Nn * Ll];
__device__ __align__(16) __half g_Bh[Hh * Hh];
__device__ __align__(16) __half g_Eh[Nn * Ll * Hh];
__device__ float4 g_ctxP4[4][Nn * (Hh / 4)];

// ---------------------------------------------------------------------------
// Helpers
// ---------------------------------------------------------------------------
__device__ __forceinline__ uint32_t smem_u32(const void* p) {
    uint32_t a;
    asm("{ .reg .u64 t; cvta.to.shared.u64 t, %1; cvt.u32.u64 %0, t; }" : "=r"(a) : "l"(p));
    return a;
}
__device__ __forceinline__ float tanh_fast(float x) {
    float e = __expf(2.0f * x);
    return 1.0f - __fdividef(2.0f, e + 1.0f);
}
__device__ __forceinline__ void ldsm_x4(uint32_t* r, uint32_t addr) {
    asm volatile("ldmatrix.sync.aligned.m8n8.x4.shared.b16 {%0,%1,%2,%3}, [%4];"
                 : "=r"(r[0]), "=r"(r[1]), "=r"(r[2]), "=r"(r[3]) : "r"(addr));
}
__device__ __forceinline__ void mma_f16(float* c, const uint32_t* a, uint32_t b0, uint32_t b1) {
    asm volatile("mma.sync.aligned.m16n8k16.row.col.f32.f16.f16.f32 "
                 "{%0,%1,%2,%3}, {%4,%5,%6,%7}, {%8,%9}, {%0,%1,%2,%3};"
                 : "+f"(c[0]), "+f"(c[1]), "+f"(c[2]), "+f"(c[3])
                 : "r"(a[0]), "r"(a[1]), "r"(a[2]), "r"(a[3]), "r"(b0), "r"(b1));
}
__device__ __forceinline__ void cp_async16(uint32_t dst, const void* src) {
    asm volatile("cp.async.cg.shared.global [%0], [%1], 16;" :: "r"(dst), "l"(src) : "memory");
}
#define CP_COMMIT() asm volatile("cp.async.commit_group;" ::: "memory")

// ---------------------------------------------------------------------------
// Convert Ws -> fp16
// ---------------------------------------------------------------------------
__global__ __launch_bounds__(256) void bconv_kernel(const float* __restrict__ Ws) {
    size_t i = (size_t)blockIdx.x * 256 + threadIdx.x;
    float4 w0 = ((const float4*)Ws)[2 * i];
    float4 w1 = ((const float4*)Ws)[2 * i + 1];
    __half2 h[4];
    h[0] = __floats2half2_rn(w0.x, w0.y);
    h[1] = __floats2half2_rn(w0.z, w0.w);
    h[2] = __floats2half2_rn(w1.x, w1.y);
    h[3] = __floats2half2_rn(w1.z, w1.w);
    ((uint4*)g_Bh)[i] = *(uint4*)h;
}

// ---------------------------------------------------------------------------
// Convert E -> fp16
// ---------------------------------------------------------------------------
__global__ __launch_bounds__(256) void econv_kernel(const float* __restrict__ E) {
    size_t i = (size_t)blockIdx.x * 256 + threadIdx.x;
    float4 w0 = ((const float4*)E)[2 * i];
    float4 w1 = ((const float4*)E)[2 * i + 1];
    __half2 h[4];
    h[0] = __floats2half2_rn(w0.x, w0.y);
    h[1] = __floats2half2_rn(w0.z, w0.w);
    h[2] = __floats2half2_rn(w1.x, w1.y);
    h[3] = __floats2half2_rn(w1.z, w1.w);
    ((uint4*)g_Eh)[i] = *(uint4*)h;
}

// ---------------------------------------------------------------------------
// dh partials: tiled GEMM, Wh read once. grid 64 = 16 k-blocks x 4 h-splits.
// ---------------------------------------------------------------------------
__global__ __launch_bounds__(256) void dh_kernel(const float* __restrict__ dec,
                                                 const float* __restrict__ Wh) {
    __shared__ float ds[64][68];
    __shared__ float ws[64][68];
    const int tid = threadIdx.x;
    const int kb = (blockIdx.x & 15) * 64;
    const int hs = blockIdx.x >> 4;
    const int n0 = (tid & 15) * 4;
    const int k0 = (tid >> 4) * 4;
    float acc[4][4] = {};
    for (int cc = 0; cc < 4; ++cc) {
        const int hb = hs * 256 + cc * 64;
        __syncthreads();
#pragma unroll
        for (int q = 0; q < 4; ++q) {
            int f4 = tid + 256 * q;
            int r = f4 >> 4;
            int col = f4 & 15;
            float4 a = *(const float4*)(dec + (size_t)r * Hh + hb + col * 4);
            ds[col * 4 + 0][r] = a.x; ds[col * 4 + 1][r] = a.y;
            ds[col * 4 + 2][r] = a.z; ds[col * 4 + 3][r] = a.w;
            float4 b = *(const float4*)(Wh + (size_t)(kb + r) * Hh + hb + col * 4);
            ws[col * 4 + 0][r] = b.x; ws[col * 4 + 1][r] = b.y;
            ws[col * 4 + 2][r] = b.z; ws[col * 4 + 3][r] = b.w;
        }
        __syncthreads();
#pragma unroll 8
        for (int h = 0; h < 64; ++h) {
            float a[4], b[4];
            *(float4*)a = *(const float4*)&ds[h][n0];
            *(float4*)b = *(const float4*)&ws[h][k0];
#pragma unroll
            for (int i = 0; i < 4; ++i)
#pragma unroll
                for (int j = 0; j < 4; ++j) acc[i][j] += a[i] * b[j];
        }
    }
#pragma unroll
    for (int i = 0; i < 4; ++i)
#pragma unroll
        for (int j = 0; j < 4; ++j)
            g_dhP[hs][(n0 + i) * Hh + kb + k0 + j] = acc[i][j];
}

// ---------------------------------------------------------------------------
// Fused score kernel: fp16 mma.sync GEMM + tanh(.)·v epilogue.
// Continuous 64-chunk pipeline, grid.y=2, NSTAGE=3, 2 CTAs/SM.
// ks loop phase-rotated per wn so same-SMSP warps destagger ldsm bursts.
// ---------------------------------------------------------------------------
#define A_BYTES 16384
#define STAGE_BYTES (2 * A_BYTES)
#define NSTAGE 3
#define SM_DH   0
#define SM_V    1024
#define SM_SRED 2048
#define SM_STG  3072
#define SM_TOTAL (SM_STG + NSTAGE * STAGE_BYTES)  // 101376

__global__ __launch_bounds__(256, 2) void score_kernel(const float* __restrict__ v) {
    extern __shared__ char smem[];
    const uint32_t sb = smem_u32(smem);
    const int tid = threadIdx.x;
    const int lane = tid & 31;
    const int wid = tid >> 5;
    const int wm = wid & 3;
    const int wn = wid >> 2;
    const int row0 = blockIdx.x * 128;
    const int n = row0 >> 10;
    const int j0 = blockIdx.y * 4;

    // ---- loader precompute ----
    uint32_t ldst[4];
    size_t gaoff[4];
    uint32_t gboff_c[4];
#pragma unroll
    for (int t = 0; t < 4; ++t) {
        int u = tid + 256 * t;
        int lrow = u >> 3, lseg = u & 7;
        ldst[t] = (uint32_t)(lrow * 128 + ((lseg ^ (lrow & 7)) << 4));
        gaoff[t] = (size_t)(row0 + lrow) * Hh + lseg * 8;
        gboff_c[t] = (uint32_t)(lrow * Hh + lseg * 8);
    }

    // ---- ldsm address bases ----
    uint32_t abase[2], axr[2], bbase[4], bxr[4];
    {
        const int aseg0 = lane >> 4;
        const int bseg0 = (lane >> 3) & 1;
#pragma unroll
        for (int mt = 0; mt < 2; ++mt) {
            int r = wm * 32 + mt * 16 + (lane & 15);
            abase[mt] = (uint32_t)(r * 128 + ((aseg0 ^ (r & 1)) << 4));
            axr[mt] = (uint32_t)(r & 6);
        }
#pragma unroll
        for (int np = 0; np < 4; ++np) {
            int r = wn * 64 + np * 16 + ((lane >> 4) << 3) + (lane & 7);
            bbase[np] = (uint32_t)(r * 128 + ((bseg0 ^ (r & 1)) << 4));
            bxr[np] = (uint32_t)(r & 6);
        }
    }
    const uint32_t ksrot = (uint32_t)(wn << 1);  // phase offset per wn

    auto cp_stage = [&](int cc2) {
        const uint32_t base = sb + SM_STG + (uint32_t)(cc2 % NSTAGE) * STAGE_BYTES;
        const int kb = (cc2 & 15) * 64;
        const uint32_t jb = (uint32_t)((j0 + (cc2 >> 4)) * 128) * Hh;
#pragma unroll
        for (int t = 0; t < 4; ++t) cp_async16(base + ldst[t], g_Eh + gaoff[t] + kb);
#pragma unroll
        for (int t = 0; t < 4; ++t)
            cp_async16(base + A_BYTES + ldst[t], g_Bh + jb + gboff_c[t] + kb);
    };

    if (tid < 128) {
        int idx = (n << 10) + j0 * 128 + tid;
        ((float*)(smem + SM_DH))[tid] =
            g_dhP[0][idx] + g_dhP[1][idx] + g_dhP[2][idx] + g_dhP[3][idx];
        ((float*)(smem + SM_V))[tid] = v[j0 * 128 + tid];
    }
    __syncthreads();

    float acc[2][8][4];
#pragma unroll
    for (int mt = 0; mt < 2; ++mt)
#pragma unroll
        for (int nt = 0; nt < 8; ++nt)
#pragma unroll
            for (int e = 0; e < 4; ++e) acc[mt][nt][e] = 0.f;

    cp_stage(0);
    CP_COMMIT();
    cp_stage(1);
    CP_COMMIT();

    for (int cc = 0; cc < 64; ++cc) {
        if (cc < 63)
            asm volatile("cp.async.wait_group 1;" ::: "memory");
        else
            asm volatile("cp.async.wait_group 0;" ::: "memory");
        __syncthreads();
        if (cc + 2 < 64) {
            cp_stage(cc + 2);
            CP_COMMIT();
        }

        const uint32_t base = sb + SM_STG + (uint32_t)(cc % NSTAGE) * STAGE_BYTES;
        const uint32_t sA = base;
        const uint32_t sB = base + A_BYTES;

#pragma unroll
        for (int ks = 0; ks < 4; ++ks) {
            const uint32_t ksx = (uint32_t)(((ks + ksrot) & 3) * 2);  // rotated slice
            uint32_t ah[2][4];
            ldsm_x4(ah[0], sA + abase[0] + ((ksx ^ axr[0]) << 4));
            ldsm_x4(ah[1], sA + abase[1] + ((ksx ^ axr[1]) << 4));
            uint32_t bb[2][4];
            ldsm_x4(bb[0], sB + bbase[0] + ((ksx ^ bxr[0]) << 4));
#pragma unroll
            for (int np = 0; np < 4; ++np) {
                if (np < 3)
                    ldsm_x4(bb[(np + 1) & 1], sB + bbase[np + 1] + ((ksx ^ bxr[np + 1]) << 4));
                const uint32_t* bq = bb[np & 1];
                mma_f16(acc[0][np * 2 + 0], ah[0], bq[0], bq[1]);
                mma_f16(acc[0][np * 2 + 1], ah[0], bq[2], bq[3]);
                mma_f16(acc[1][np * 2 + 0], ah[1], bq[0], bq[1]);
                mma_f16(acc[1][np * 2 + 1], ah[1], bq[2], bq[3]);
            }
        }

        if ((cc & 15) == 15) {
            const int jloc = cc >> 4;
            const int jglob = j0 + jloc;
            const int jb1 = jloc & 1;
            if (jloc < 3 && tid < 128) {
                int idx = (n << 10) + (jglob + 1) * 128 + tid;
                ((float*)(smem + SM_DH + (1 - jb1) * 512))[tid] =
                    g_dhP[0][idx] + g_dhP[1][idx] + g_dhP[2][idx] + g_dhP[3][idx];
                ((float*)(smem + SM_V + (1 - jb1) * 512))[tid] =
                    v[(jglob + 1) * 128 + tid];
            }
            const float* dhs = (const float*)(smem + SM_DH + jb1 * 512);
            const float* vs = (const float*)(smem + SM_V + jb1 * 512);
            float part[4] = {0.f, 0.f, 0.f, 0.f};
#pragma unroll
            for (int mt = 0; mt < 2; ++mt)
#pragma unroll
                for (int nt = 0; nt < 8; ++nt)
#pragma unroll
                    for (int e = 0; e < 4; ++e) {
                        int col = wn * 64 + nt * 8 + (lane & 3) * 2 + (e & 1);
                        part[mt * 2 + (e >> 1)] +=
                            tanh_fast(acc[mt][nt][e] + dhs[col]) * vs[col];
                        acc[mt][nt][e] = 0.f;
                    }
#pragma unroll
            for (int p = 0; p < 4; ++p) {
                part[p] += __shfl_xor_sync(0xffffffffu, part[p], 1);
                part[p] += __shfl_xor_sync(0xffffffffu, part[p], 2);
            }
            float* sred = (float*)(smem + SM_SRED);
            if ((lane & 3) == 0) {
#pragma unroll
                for (int mt = 0; mt < 2; ++mt)
#pragma unroll
                    for (int rr = 0; rr < 2; ++rr) {
                        int row = wm * 32 + mt * 16 + (lane >> 2) + rr * 8;
                        sred[row * 2 + wn] = part[mt * 2 + rr];
                    }
            }
            __syncthreads();
            if (tid < 128)
                g_scoreP[jglob][row0 + tid] = sred[tid * 2] + sred[tid * 2 + 1];
        }
    }
}

// ---------------------------------------------------------------------------
// Context with inline softmax: block (n, lc) recomputes row-n softmax
// (deterministic, redundant x4), writes attn quarter lc, then accumulates
// its L-quarter context partial from fp16 E.
// ---------------------------------------------------------------------------
__global__ __launch_bounds__(128) void context_kernel(const int* __restrict__ mask,
                                                      float* __restrict__ attn) {
    __shared__ float sa[256];
    __shared__ float red[128];
    const int n = blockIdx.x, lc = blockIdx.y;
    const int tid = threadIdx.x;

    // --- inline softmax over row n ---
    float s[8];
    int msk[8];
    float lmax = -CUDART_INF_F;
#pragma unroll
    for (int q = 0; q < 8; ++q) {
        int l = tid + 128 * q;
        msk[q] = mask[n * Ll + l];
        float a = 0.f;
#pragma unroll
        for (int p = 0; p < 8; ++p) a += g_scoreP[p][n * Ll + l];
        s[q] = a;
        if (!msk[q]) lmax = fmaxf(lmax, s[q]);
    }
    red[tid] = lmax;
    __syncthreads();
    for (int o = 64; o; o >>= 1) {
        if (tid < o) red[tid] = fmaxf(red[tid], red[tid + o]);
        __syncthreads();
    }
    const float mx = red[0];
    __syncthreads();
    float lsum = 0.f;
    float pv[8];
#pragma unroll
    for (int q = 0; q < 8; ++q) {
        pv[q] = msk[q] ? 0.f : __expf(s[q] - mx);
        lsum += pv[q];
    }
    red[tid] = lsum;
    __syncthreads();
    for (int o = 64; o; o >>= 1) {
        if (tid < o) red[tid] += red[tid + o];
        __syncthreads();
    }
    const float inv = 1.0f / red[0];
    __syncthreads();
    // write attn for our quarter; fill sa
#pragma unroll
    for (int q = 0; q < 8; ++q) {
        int l = tid + 128 * q;
        float w = pv[q] * inv;
        if ((l >> 8) == lc) {
            attn[n * Ll + l] = w;
            sa[l - lc * 256] = w;
        }
    }
    __syncthreads();

    // --- context partial over L-quarter lc ---
    const uint4* Ep = (const uint4*)(g_Eh + (size_t)n * Ll * Hh) +
                      (size_t)(lc * 256) * 128 + tid;
    float acc[8] = {};
#pragma unroll 4
    for (int l = 0; l < 256; ++l) {
        uint4 u = Ep[(size_t)l * 128];
        const __half2* h2 = (const __half2*)&u;
        float a = sa[l];
#pragma unroll
        for (int q = 0; q < 4; ++q) {
            float2 f = __half22float2(h2[q]);
            acc[q * 2 + 0] += a * f.x;
            acc[q * 2 + 1] += a * f.y;
        }
    }
    float4* dst = &g_ctxP4[lc][n * 256 + tid * 2];
    dst[0] = make_float4(acc[0], acc[1], acc[2], acc[3]);
    dst[1] = make_float4(acc[4], acc[5], acc[6], acc[7]);
}

__global__ __launch_bounds__(256) void ctx_reduce_kernel(float4* __restrict__ ctx4) {
    int i = blockIdx.x * 256 + threadIdx.x;
    float4 a = g_ctxP4[0][i], b = g_ctxP4[1][i], c = g_ctxP4[2][i], d = g_ctxP4[3][i];
    ctx4[i] = make_float4(a.x + b.x + c.x + d.x, a.y + b.y + c.y + d.y,
                          a.z + b.z + c.z + d.z, a.w + b.w + c.w + d.w);
}

// ---------------------------------------------------------------------------
extern "C" void kernel_launch(void* const* d_in, const int* in_sizes, int n_in,
                              void* d_out, int out_size) {
    const float* dec  = (const float*)d_in[0];
    const float* E    = (const float*)d_in[1];
    const int*   mask = (const int*)  d_in[2];
    const float* Wh   = (const float*)d_in[3];
    const float* Ws   = (const float*)d_in[4];
    const float* v    = (const float*)d_in[5];

    float* out  = (float*)d_out;
    float* ctx  = out;
    float* attn = out + Nn * Hh;

    cudaFuncSetAttribute(score_kernel, cudaFuncAttributeMaxDynamicSharedMemorySize, SM_TOTAL);

    bconv_kernel<<<(Hh * Hh / 8) / 256, 256>>>(Ws);
    econv_kernel<<<(Nn * Ll * Hh / 8) / 256, 256>>>(E);
    dh_kernel<<<64, 256>>>(dec, Wh);
    score_kernel<<<dim3((Nn * Ll) / 128, 2), 256, SM_TOTAL>>>(v);
    context_kernel<<<dim3(Nn, 4), 128>>>(mask, attn);
    ctx_reduce_kernel<<<(Nn * Hh / 4) / 256, 256>>>((float4*)ctx);
}

// round 11
// speedup vs baseline: 1.0530x; 1.0530x over previous
#include <cuda_runtime.h>
#include <cuda_fp16.h>
#include <math_constants.h>
#include <cstdint>

#define Nn 64
#define Ll 1024
#define Hh 1024

// ---------------------------------------------------------------------------
// Device scratch
// ---------------------------------------------------------------------------
__device__ float g_dhP[4][Nn * Hh];
__device__ float g_scoreP[8][Nn * Ll];
__device__ __align__(16) __half g_Bh[Hh * Hh];
__device__ __align__(16) __half g_Eh[Nn * Ll * Hh];
__device__ float4 g_ctxP4[4][Nn * (Hh / 4)];

// ---------------------------------------------------------------------------
// Helpers
// ---------------------------------------------------------------------------
__device__ __forceinline__ uint32_t smem_u32(const void* p) {
    uint32_t a;
    asm("{ .reg .u64 t; cvta.to.shared.u64 t, %1; cvt.u32.u64 %0, t; }" : "=r"(a) : "l"(p));
    return a;
}
__device__ __forceinline__ float tanh_fast(float x) {
    float e = __expf(2.0f * x);
    return 1.0f - __fdividef(2.0f, e + 1.0f);
}
__device__ __forceinline__ void ldsm_x4(uint32_t* r, uint32_t addr) {
    asm volatile("ldmatrix.sync.aligned.m8n8.x4.shared.b16 {%0,%1,%2,%3}, [%4];"
                 : "=r"(r[0]), "=r"(r[1]), "=r"(r[2]), "=r"(r[3]) : "r"(addr));
}
__device__ __forceinline__ void mma_f16(float* c, const uint32_t* a, uint32_t b0, uint32_t b1) {
    asm volatile("mma.sync.aligned.m16n8k16.row.col.f32.f16.f16.f32 "
                 "{%0,%1,%2,%3}, {%4,%5,%6,%7}, {%8,%9}, {%0,%1,%2,%3};"
                 : "+f"(c[0]), "+f"(c[1]), "+f"(c[2]), "+f"(c[3])
                 : "r"(a[0]), "r"(a[1]), "r"(a[2]), "r"(a[3]), "r"(b0), "r"(b1));
}
__device__ __forceinline__ void cp_async16(uint32_t dst, const void* src) {
    asm volatile("cp.async.cg.shared.global [%0], [%1], 16;" :: "r"(dst), "l"(src) : "memory");
}

// ---- mbarrier ops (generic PTX, sm_80/90; no arch-specific features) ----
#define MBAR_INIT(addr, cnt) \
    asm volatile("mbarrier.init.shared.b64 [%0], %1;" :: "r"((uint32_t)(addr)), "r"((uint32_t)(cnt)) : "memory")
#define MBAR_ARRIVE(addr) \
    asm volatile("{\n\t.reg .b64 t;\n\tmbarrier.arrive.shared.b64 t, [%0];\n\t}" \
                 :: "r"((uint32_t)(addr)) : "memory")
#define CP_ASYNC_MBAR_ARRIVE_NOINC(addr) \
    asm volatile("cp.async.mbarrier.arrive.noinc.shared.b64 [%0];" :: "r"((uint32_t)(addr)) : "memory")
#define MBAR_WAIT_PARITY(addr, parity) do {                                              \
    uint32_t _mbar = (uint32_t)(addr);                                                   \
    uint32_t _par  = (uint32_t)(parity);                                                 \
    uint32_t _done;                                                                      \
    asm volatile("{\n\t.reg .pred p;\n\t"                                                \
        "mbarrier.try_wait.parity.acquire.cta.shared::cta.b64 p, [%1], %2;\n\t"          \
        "selp.b32 %0, 1, 0, p;\n\t}" : "=r"(_done) : "r"(_mbar), "r"(_par) : "memory");  \
    if (!_done) {                                                                        \
        asm volatile("{\n\t.reg .pred P1;\n\t"                                           \
            "WL_%=:\n\t"                                                                 \
            "mbarrier.try_wait.parity.acquire.cta.shared::cta.b64 P1, [%0], %1, 0x989680;\n\t" \
            "@P1 bra.uni WD_%=;\n\t"                                                     \
            "bra.uni WL_%=;\n\t"                                                         \
            "WD_%=:\n\t}" :: "r"(_mbar), "r"(_par) : "memory");                          \
    }                                                                                    \
} while (0)

// ---------------------------------------------------------------------------
// Convert Ws -> fp16
// ---------------------------------------------------------------------------
__global__ __launch_bounds__(256) void bconv_kernel(const float* __restrict__ Ws) {
    size_t i = (size_t)blockIdx.x * 256 + threadIdx.x;
    float4 w0 = ((const float4*)Ws)[2 * i];
    float4 w1 = ((const float4*)Ws)[2 * i + 1];
    __half2 h[4];
    h[0] = __floats2half2_rn(w0.x, w0.y);
    h[1] = __floats2half2_rn(w0.z, w0.w);
    h[2] = __floats2half2_rn(w1.x, w1.y);
    h[3] = __floats2half2_rn(w1.z, w1.w);
    ((uint4*)g_Bh)[i] = *(uint4*)h;
}

// ---------------------------------------------------------------------------
// Convert E -> fp16
// ---------------------------------------------------------------------------
__global__ __launch_bounds__(256) void econv_kernel(const float* __restrict__ E) {
    size_t i = (size_t)blockIdx.x * 256 + threadIdx.x;
    float4 w0 = ((const float4*)E)[2 * i];
    float4 w1 = ((const float4*)E)[2 * i + 1];
    __half2 h[4];
    h[0] = __floats2half2_rn(w0.x, w0.y);
    h[1] = __floats2half2_rn(w0.z, w0.w);
    h[2] = __floats2half2_rn(w1.x, w1.y);
    h[3] = __floats2half2_rn(w1.z, w1.w);
    ((uint4*)g_Eh)[i] = *(uint4*)h;
}

// ---------------------------------------------------------------------------
// dh partials: tiled GEMM, Wh read once. grid 64 = 16 k-blocks x 4 h-splits.
// ---------------------------------------------------------------------------
__global__ __launch_bounds__(256) void dh_kernel(const float* __restrict__ dec,
                                                 const float* __restrict__ Wh) {
    __shared__ float ds[64][68];
    __shared__ float ws[64][68];
    const int tid = threadIdx.x;
    const int kb = (blockIdx.x & 15) * 64;
    const int hs = blockIdx.x >> 4;
    const int n0 = (tid & 15) * 4;
    const int k0 = (tid >> 4) * 4;
    float acc[4][4] = {};
    for (int cc = 0; cc < 4; ++cc) {
        const int hb = hs * 256 + cc * 64;
        __syncthreads();
#pragma unroll
        for (int q = 0; q < 4; ++q) {
            int f4 = tid + 256 * q;
            int r = f4 >> 4;
            int col = f4 & 15;
            float4 a = *(const float4*)(dec + (size_t)r * Hh + hb + col * 4);
            ds[col * 4 + 0][r] = a.x; ds[col * 4 + 1][r] = a.y;
            ds[col * 4 + 2][r] = a.z; ds[col * 4 + 3][r] = a.w;
            float4 b = *(const float4*)(Wh + (size_t)(kb + r) * Hh + hb + col * 4);
            ws[col * 4 + 0][r] = b.x; ws[col * 4 + 1][r] = b.y;
            ws[col * 4 + 2][r] = b.z; ws[col * 4 + 3][r] = b.w;
        }
        __syncthreads();
#pragma unroll 8
        for (int h = 0; h < 64; ++h) {
            float a[4], b[4];
            *(float4*)a = *(const float4*)&ds[h][n0];
            *(float4*)b = *(const float4*)&ws[h][k0];
#pragma unroll
            for (int i = 0; i < 4; ++i)
#pragma unroll
                for (int j = 0; j < 4; ++j) acc[i][j] += a[i] * b[j];
        }
    }
#pragma unroll
    for (int i = 0; i < 4; ++i)
#pragma unroll
        for (int j = 0; j < 4; ++j)
            g_dhP[hs][(n0 + i) * Hh + kb + k0 + j] = acc[i][j];
}

// ---------------------------------------------------------------------------
// Fused score kernel: fp16 mma.sync GEMM + tanh(.)·v epilogue.
// mbarrier producer/consumer pipeline (3 stages) — no per-chunk block
// barrier; warps may skew up to 1 chunk. grid.y=2, 2 CTAs/SM.
// ---------------------------------------------------------------------------
#define A_BYTES 16384
#define STAGE_BYTES (2 * A_BYTES)
#define NSTAGE 3
#define SM_DH   0                 // 2 x 512B
#define SM_V    1024              // 2 x 512B
#define SM_SRED 2048              // 1024B
#define SM_MBAR 3072              // 3 stages x (full,empty) x 8B = 48B (pad 1KB)
#define SM_STG  4096
#define SM_TOTAL (SM_STG + NSTAGE * STAGE_BYTES)  // 102400

__global__ __launch_bounds__(256, 2) void score_kernel(const float* __restrict__ v) {
    extern __shared__ char smem[];
    const uint32_t sb = smem_u32(smem);
    const int tid = threadIdx.x;
    const int lane = tid & 31;
    const int wid = tid >> 5;
    const int wm = wid & 3;
    const int wn = wid >> 2;
    const int row0 = blockIdx.x * 128;
    const int n = row0 >> 10;
    const int j0 = blockIdx.y * 4;

    // ---- loader precompute ----
    uint32_t ldst[4];
    size_t gaoff[4];
    uint32_t gboff_c[4];
#pragma unroll
    for (int t = 0; t < 4; ++t) {
        int u = tid + 256 * t;
        int lrow = u >> 3, lseg = u & 7;
        ldst[t] = (uint32_t)(lrow * 128 + ((lseg ^ (lrow & 7)) << 4));
        gaoff[t] = (size_t)(row0 + lrow) * Hh + lseg * 8;
        gboff_c[t] = (uint32_t)(lrow * Hh + lseg * 8);
    }

    // ---- ldsm address bases ----
    uint32_t abase[2], axr[2], bbase[4], bxr[4];
    {
        const int aseg0 = lane >> 4;
        const int bseg0 = (lane >> 3) & 1;
#pragma unroll
        for (int mt = 0; mt < 2; ++mt) {
            int r = wm * 32 + mt * 16 + (lane & 15);
            abase[mt] = (uint32_t)(r * 128 + ((aseg0 ^ (r & 1)) << 4));
            axr[mt] = (uint32_t)(r & 6);
        }
#pragma unroll
        for (int np = 0; np < 4; ++np) {
            int r = wn * 64 + np * 16 + ((lane >> 4) << 3) + (lane & 7);
            bbase[np] = (uint32_t)(r * 128 + ((bseg0 ^ (r & 1)) << 4));
            bxr[np] = (uint32_t)(r & 6);
        }
    }
    const uint32_t ksrot = (uint32_t)(wn << 1);

    // fill stage for chunk cc2: cp.asyncs + deferred arrival on full barrier
    auto fill = [&](int cc2) {
        const int s2 = cc2 % NSTAGE;
        const uint32_t base = sb + SM_STG + (uint32_t)s2 * STAGE_BYTES;
        const int kb = (cc2 & 15) * 64;
        const uint32_t jb = (uint32_t)((j0 + (cc2 >> 4)) * 128) * Hh;
#pragma unroll
        for (int t = 0; t < 4; ++t) cp_async16(base + ldst[t], g_Eh + gaoff[t] + kb);
#pragma unroll
        for (int t = 0; t < 4; ++t)
            cp_async16(base + A_BYTES + ldst[t], g_Bh + jb + gboff_c[t] + kb);
        CP_ASYNC_MBAR_ARRIVE_NOINC(sb + SM_MBAR + s2 * 16);  // full[s2]
    };

    // init barriers + dh/v for first j-block
    if (tid == 0) {
#pragma unroll
        for (int s = 0; s < NSTAGE; ++s) {
            MBAR_INIT(sb + SM_MBAR + s * 16, 256);      // full[s]
            MBAR_INIT(sb + SM_MBAR + s * 16 + 8, 256);  // empty[s]
        }
    }
    if (tid < 128) {
        int idx = (n << 10) + j0 * 128 + tid;
        ((float*)(smem + SM_DH))[tid] =
            g_dhP[0][idx] + g_dhP[1][idx] + g_dhP[2][idx] + g_dhP[3][idx];
        ((float*)(smem + SM_V))[tid] = v[j0 * 128 + tid];
    }
    __syncthreads();

    float acc[2][8][4];
#pragma unroll
    for (int mt = 0; mt < 2; ++mt)
#pragma unroll
        for (int nt = 0; nt < 8; ++nt)
#pragma unroll
            for (int e = 0; e < 4; ++e) acc[mt][nt][e] = 0.f;

    fill(0);
    fill(1);

    for (int cc = 0; cc < 64; ++cc) {
        const int s = cc % NSTAGE;
        // consumer: wait stage full (parity = use count & 1)
        MBAR_WAIT_PARITY(sb + SM_MBAR + s * 16, (cc / 3) & 1);

        const uint32_t base = sb + SM_STG + (uint32_t)s * STAGE_BYTES;
        const uint32_t sA = base;
        const uint32_t sB = base + A_BYTES;

#pragma unroll
        for (int ks = 0; ks < 4; ++ks) {
            const uint32_t ksx = (uint32_t)(((ks + ksrot) & 3) * 2);
            uint32_t ah[2][4];
            ldsm_x4(ah[0], sA + abase[0] + ((ksx ^ axr[0]) << 4));
            ldsm_x4(ah[1], sA + abase[1] + ((ksx ^ axr[1]) << 4));
            uint32_t bb[2][4];
            ldsm_x4(bb[0], sB + bbase[0] + ((ksx ^ bxr[0]) << 4));
#pragma unroll
            for (int np = 0; np < 4; ++np) {
                if (np < 3)
                    ldsm_x4(bb[(np + 1) & 1], sB + bbase[np + 1] + ((ksx ^ bxr[np + 1]) << 4));
                const uint32_t* bq = bb[np & 1];
                mma_f16(acc[0][np * 2 + 0], ah[0], bq[0], bq[1]);
                mma_f16(acc[0][np * 2 + 1], ah[0], bq[2], bq[3]);
                mma_f16(acc[1][np * 2 + 0], ah[1], bq[0], bq[1]);
                mma_f16(acc[1][np * 2 + 1], ah[1], bq[2], bq[3]);
            }
        }
        // MMA operands depend on all ldsm results -> stage reads done; release it.
        MBAR_ARRIVE(sb + SM_MBAR + s * 16 + 8);  // empty[s]

        // producer: refill stage for chunk cc+2
        const int c2 = cc + 2;
        if (c2 < 64) {
            const int s2 = c2 % NSTAGE;
            if (c2 >= NSTAGE)
                MBAR_WAIT_PARITY(sb + SM_MBAR + s2 * 16 + 8, (c2 / 3 - 1) & 1);
            fill(c2);
        }

        if ((cc & 15) == 15) {
            const int jloc = cc >> 4;
            const int jglob = j0 + jloc;
            const int jb1 = jloc & 1;
            if (jloc < 3 && tid < 128) {
                int idx = (n << 10) + (jglob + 1) * 128 + tid;
                ((float*)(smem + SM_DH + (1 - jb1) * 512))[tid] =
                    g_dhP[0][idx] + g_dhP[1][idx] + g_dhP[2][idx] + g_dhP[3][idx];
                ((float*)(smem + SM_V + (1 - jb1) * 512))[tid] =
                    v[(jglob + 1) * 128 + tid];
            }
            const float* dhs = (const float*)(smem + SM_DH + jb1 * 512);
            const float* vs = (const float*)(smem + SM_V + jb1 * 512);
            float part[4] = {0.f, 0.f, 0.f, 0.f};
#pragma unroll
            for (int mt = 0; mt < 2; ++mt)
#pragma unroll
                for (int nt = 0; nt < 8; ++nt)
#pragma unroll
                    for (int e = 0; e < 4; ++e) {
                        int col = wn * 64 + nt * 8 + (lane & 3) * 2 + (e & 1);
                        part[mt * 2 + (e >> 1)] +=
                            tanh_fast(acc[mt][nt][e] + dhs[col]) * vs[col];
                        acc[mt][nt][e] = 0.f;
                    }
#pragma unroll
            for (int p = 0; p < 4; ++p) {
                part[p] += __shfl_xor_sync(0xffffffffu, part[p], 1);
                part[p] += __shfl_xor_sync(0xffffffffu, part[p], 2);
            }
            float* sred = (float*)(smem + SM_SRED);
            __syncthreads();  // all warps done with prior sred use
            if ((lane & 3) == 0) {
#pragma unroll
                for (int mt = 0; mt < 2; ++mt)
#pragma unroll
                    for (int rr = 0; rr < 2; ++rr) {
                        int row = wm * 32 + mt * 16 + (lane >> 2) + rr * 8;
                        sred[row * 2 + wn] = part[mt * 2 + rr];
                    }
            }
            __syncthreads();
            if (tid < 128)
                g_scoreP[jglob][row0 + tid] = sred[tid * 2] + sred[tid * 2 + 1];
        }
    }
}

// ---------------------------------------------------------------------------
// Context with inline softmax (per (n, L-quarter) block)
// ---------------------------------------------------------------------------
__global__ __launch_bounds__(128) void context_kernel(const int* __restrict__ mask,
                                                      float* __restrict__ attn) {
    __shared__ float sa[256];
    __shared__ float red[128];
    const int n = blockIdx.x, lc = blockIdx.y;
    const int tid = threadIdx.x;

    float s[8];
    int msk[8];
    float lmax = -CUDART_INF_F;
#pragma unroll
    for (int q = 0; q < 8; ++q) {
        int l = tid + 128 * q;
        msk[q] = mask[n * Ll + l];
        float a = 0.f;
#pragma unroll
        for (int p = 0; p < 8; ++p) a += g_scoreP[p][n * Ll + l];
        s[q] = a;
        if (!msk[q]) lmax = fmaxf(lmax, s[q]);
    }
    red[tid] = lmax;
    __syncthreads();
    for (int o = 64; o; o >>= 1) {
        if (tid < o) red[tid] = fmaxf(red[tid], red[tid + o]);
        __syncthreads();
    }
    const float mx = red[0];
    __syncthreads();
    float lsum = 0.f;
    float pv[8];
#pragma unroll
    for (int q = 0; q < 8; ++q) {
        pv[q] = msk[q] ? 0.f : __expf(s[q] - mx);
        lsum += pv[q];
    }
    red[tid] = lsum;
    __syncthreads();
    for (int o = 64; o; o >>= 1) {
        if (tid < o) red[tid] += red[tid + o];
        __syncthreads();
    }
    const float inv = 1.0f / red[0];
    __syncthreads();
#pragma unroll
    for (int q = 0; q < 8; ++q) {
        int l = tid + 128 * q;
        float w = pv[q] * inv;
        if ((l >> 8) == lc) {
            attn[n * Ll + l] = w;
            sa[l - lc * 256] = w;
        }
    }
    __syncthreads();

    const uint4* Ep = (const uint4*)(g_Eh + (size_t)n * Ll * Hh) +
                      (size_t)(lc * 256) * 128 + tid;
    float acc[8] = {};
#pragma unroll 4
    for (int l = 0; l < 256; ++l) {
        uint4 u = Ep[(size_t)l * 128];
        const __half2* h2 = (const __half2*)&u;
        float a = sa[l];
#pragma unroll
        for (int q = 0; q < 4; ++q) {
            float2 f = __half22float2(h2[q]);
            acc[q * 2 + 0] += a * f.x;
            acc[q * 2 + 1] += a * f.y;
        }
    }
    float4* dst = &g_ctxP4[lc][n * 256 + tid * 2];
    dst[0] = make_float4(acc[0], acc[1], acc[2], acc[3]);
    dst[1] = make_float4(acc[4], acc[5], acc[6], acc[7]);
}

__global__ __launch_bounds__(256) void ctx_reduce_kernel(float4* __restrict__ ctx4) {
    int i = blockIdx.x * 256 + threadIdx.x;
    float4 a = g_ctxP4[0][i], b = g_ctxP4[1][i], c = g_ctxP4[2][i], d = g_ctxP4[3][i];
    ctx4[i] = make_float4(a.x + b.x + c.x + d.x, a.y + b.y + c.y + d.y,
                          a.z + b.z + c.z + d.z, a.w + b.w + c.w + d.w);
}

// ---------------------------------------------------------------------------
extern "C" void kernel_launch(void* const* d_in, const int* in_sizes, int n_in,
                              void* d_out, int out_size) {
    const float* dec  = (const float*)d_in[0];
    const float* E    = (const float*)d_in[1];
    const int*   mask = (const int*)  d_in[2];
    const float* Wh   = (const float*)d_in[3];
    const float* Ws   = (const float*)d_in[4];
    const float* v    = (const float*)d_in[5];

    float* out  = (float*)d_out;
    float* ctx  = out;
    float* attn = out + Nn * Hh;

    cudaFuncSetAttribute(score_kernel, cudaFuncAttributeMaxDynamicSharedMemorySize, SM_TOTAL);

    bconv_kernel<<<(Hh * Hh / 8) / 256, 256>>>(Ws);
    econv_kernel<<<(Nn * Ll * Hh / 8) / 256, 256>>>(E);
    dh_kernel<<<64, 256>>>(dec, Wh);
    score_kernel<<<dim3((Nn * Ll) / 128, 2), 256, SM_TOTAL>>>(v);
    context_kernel<<<dim3(Nn, 4), 128>>>(mask, attn);
    ctx_reduce_kernel<<<(Nn * Hh / 4) / 256, 256>>>((float4*)ctx);
}

// round 12
// speedup vs baseline: 1.4885x; 1.4137x over previous
#include <cuda_runtime.h>
#include <cuda_fp16.h>
#include <math_constants.h>
#include <cstdint>

#define Nn 64
#define Ll 1024
#define Hh 1024

// ---------------------------------------------------------------------------
// Device scratch
// ---------------------------------------------------------------------------
__device__ float g_dhP[4][Nn * Hh];
__device__ float g_scorePC[8][Nn * Ll];   // compact-row score partials
__device__ int   g_gidx[Nn * Ll];         // per-n compacted unmasked l indices
__device__ int   g_cnt[Nn];               // unmasked count per n
__device__ __align__(16) __half g_Bh[Hh * Hh];
__device__ __align__(16) __half g_Eh[Nn * Ll * Hh];
__device__ float4 g_ctxP4[4][Nn * (Hh / 4)];

// ---------------------------------------------------------------------------
// Helpers
// ---------------------------------------------------------------------------
__device__ __forceinline__ uint32_t smem_u32(const void* p) {
    uint32_t a;
    asm("{ .reg .u64 t; cvta.to.shared.u64 t, %1; cvt.u32.u64 %0, t; }" : "=r"(a) : "l"(p));
    return a;
}
__device__ __forceinline__ float tanh_fast(float x) {
    float e = __expf(2.0f * x);
    return 1.0f - __fdividef(2.0f, e + 1.0f);
}
__device__ __forceinline__ void ldsm_x4(uint32_t* r, uint32_t addr) {
    asm volatile("ldmatrix.sync.aligned.m8n8.x4.shared.b16 {%0,%1,%2,%3}, [%4];"
                 : "=r"(r[0]), "=r"(r[1]), "=r"(r[2]), "=r"(r[3]) : "r"(addr));
}
__device__ __forceinline__ void mma_f16(float* c, const uint32_t* a, uint32_t b0, uint32_t b1) {
    asm volatile("mma.sync.aligned.m16n8k16.row.col.f32.f16.f16.f32 "
                 "{%0,%1,%2,%3}, {%4,%5,%6,%7}, {%8,%9}, {%0,%1,%2,%3};"
                 : "+f"(c[0]), "+f"(c[1]), "+f"(c[2]), "+f"(c[3])
                 : "r"(a[0]), "r"(a[1]), "r"(a[2]), "r"(a[3]), "r"(b0), "r"(b1));
}
__device__ __forceinline__ void cp_async16(uint32_t dst, const void* src) {
    asm volatile("cp.async.cg.shared.global [%0], [%1], 16;" :: "r"(dst), "l"(src) : "memory");
}

// ---- mbarrier ops (generic PTX) ----
#define MBAR_INIT(addr, cnt) \
    asm volatile("mbarrier.init.shared.b64 [%0], %1;" :: "r"((uint32_t)(addr)), "r"((uint32_t)(cnt)) : "memory")
#define MBAR_ARRIVE(addr) \
    asm volatile("{\n\t.reg .b64 t;\n\tmbarrier.arrive.shared.b64 t, [%0];\n\t}" \
                 :: "r"((uint32_t)(addr)) : "memory")
#define CP_ASYNC_MBAR_ARRIVE_NOINC(addr) \
    asm volatile("cp.async.mbarrier.arrive.noinc.shared.b64 [%0];" :: "r"((uint32_t)(addr)) : "memory")
#define MBAR_WAIT_PARITY(addr, parity) do {                                              \
    uint32_t _mbar = (uint32_t)(addr);                                                   \
    uint32_t _par  = (uint32_t)(parity);                                                 \
    uint32_t _done;                                                                      \
    asm volatile("{\n\t.reg .pred p;\n\t"                                                \
        "mbarrier.try_wait.parity.acquire.cta.shared::cta.b64 p, [%1], %2;\n\t"          \
        "selp.b32 %0, 1, 0, p;\n\t}" : "=r"(_done) : "r"(_mbar), "r"(_par) : "memory");  \
    if (!_done) {                                                                        \
        asm volatile("{\n\t.reg .pred P1;\n\t"                                           \
            "WL_%=:\n\t"                                                                 \
            "mbarrier.try_wait.parity.acquire.cta.shared::cta.b64 P1, [%0], %1, 0x989680;\n\t" \
            "@P1 bra.uni WD_%=;\n\t"                                                     \
            "bra.uni WL_%=;\n\t"                                                         \
            "WD_%=:\n\t}" :: "r"(_mbar), "r"(_par) : "memory");                          \
    }                                                                                    \
} while (0)

// ---------------------------------------------------------------------------
// Convert Ws -> fp16
// ---------------------------------------------------------------------------
__global__ __launch_bounds__(256) void bconv_kernel(const float* __restrict__ Ws) {
    size_t i = (size_t)blockIdx.x * 256 + threadIdx.x;
    float4 w0 = ((const float4*)Ws)[2 * i];
    float4 w1 = ((const float4*)Ws)[2 * i + 1];
    __half2 h[4];
    h[0] = __floats2half2_rn(w0.x, w0.y);
    h[1] = __floats2half2_rn(w0.z, w0.w);
    h[2] = __floats2half2_rn(w1.x, w1.y);
    h[3] = __floats2half2_rn(w1.z, w1.w);
    ((uint4*)g_Bh)[i] = *(uint4*)h;
}

// ---------------------------------------------------------------------------
// Convert E -> fp16
// ---------------------------------------------------------------------------
__global__ __launch_bounds__(256) void econv_kernel(const float* __restrict__ E) {
    size_t i = (size_t)blockIdx.x * 256 + threadIdx.x;
    float4 w0 = ((const float4*)E)[2 * i];
    float4 w1 = ((const float4*)E)[2 * i + 1];
    __half2 h[4];
    h[0] = __floats2half2_rn(w0.x, w0.y);
    h[1] = __floats2half2_rn(w0.z, w0.w);
    h[2] = __floats2half2_rn(w1.x, w1.y);
    h[3] = __floats2half2_rn(w1.z, w1.w);
    ((uint4*)g_Eh)[i] = *(uint4*)h;
}

// ---------------------------------------------------------------------------
// Compact kernel: per n, ordered list of unmasked l's; zero attn; counts.
// ---------------------------------------------------------------------------
__global__ __launch_bounds__(256) void compact_kernel(const int* __restrict__ mask,
                                                      float* __restrict__ attn) {
    __shared__ int sc[256];
    __shared__ int stotal;
    const int n = blockIdx.x;
    const int tid = threadIdx.x;
    int m[4];
    int c = 0;
#pragma unroll
    for (int q = 0; q < 4; ++q) {
        m[q] = mask[(n << 10) + tid * 4 + q];
        if (!m[q]) ++c;
        attn[(n << 10) + tid * 4 + q] = 0.f;   // masked stay exactly 0
    }
    sc[tid] = c;
    __syncthreads();
    // inclusive Hillis-Steele scan
    for (int off = 1; off < 256; off <<= 1) {
        int vv = (tid >= off) ? sc[tid - off] : 0;
        __syncthreads();
        sc[tid] += vv;
        __syncthreads();
    }
    int base = sc[tid] - c;
    if (tid == 255) {
        stotal = sc[255];
        g_cnt[n] = sc[255];
    }
#pragma unroll
    for (int q = 0; q < 4; ++q)
        if (!m[q]) g_gidx[(n << 10) + base++] = tid * 4 + q;
    __syncthreads();
    for (int r = stotal + tid; r < Ll; r += 256) g_gidx[(n << 10) + r] = 0;  // pad
}

// ---------------------------------------------------------------------------
// dh partials: tiled GEMM, Wh read once.
// ---------------------------------------------------------------------------
__global__ __launch_bounds__(256) void dh_kernel(const float* __restrict__ dec,
                                                 const float* __restrict__ Wh) {
    __shared__ float ds[64][68];
    __shared__ float ws[64][68];
    const int tid = threadIdx.x;
    const int kb = (blockIdx.x & 15) * 64;
    const int hs = blockIdx.x >> 4;
    const int n0 = (tid & 15) * 4;
    const int k0 = (tid >> 4) * 4;
    float acc[4][4] = {};
    for (int cc = 0; cc < 4; ++cc) {
        const int hb = hs * 256 + cc * 64;
        __syncthreads();
#pragma unroll
        for (int q = 0; q < 4; ++q) {
            int f4 = tid + 256 * q;
            int r = f4 >> 4;
            int col = f4 & 15;
            float4 a = *(const float4*)(dec + (size_t)r * Hh + hb + col * 4);
            ds[col * 4 + 0][r] = a.x; ds[col * 4 + 1][r] = a.y;
            ds[col * 4 + 2][r] = a.z; ds[col * 4 + 3][r] = a.w;
            float4 b = *(const float4*)(Wh + (size_t)(kb + r) * Hh + hb + col * 4);
            ws[col * 4 + 0][r] = b.x; ws[col * 4 + 1][r] = b.y;
            ws[col * 4 + 2][r] = b.z; ws[col * 4 + 3][r] = b.w;
        }
        __syncthreads();
#pragma unroll 8
        for (int h = 0; h < 64; ++h) {
            float a[4], b[4];
            *(float4*)a = *(const float4*)&ds[h][n0];
            *(float4*)b = *(const float4*)&ws[h][k0];
#pragma unroll
            for (int i = 0; i < 4; ++i)
#pragma unroll
                for (int j = 0; j < 4; ++j) acc[i][j] += a[i] * b[j];
        }
    }
#pragma unroll
    for (int i = 0; i < 4; ++i)
#pragma unroll
        for (int j = 0; j < 4; ++j)
            g_dhP[hs][(n0 + i) * Hh + kb + k0 + j] = acc[i][j];
}

// ---------------------------------------------------------------------------
// Fused score kernel on COMPACTED rows: fp16 mma.sync + tanh(.)·v epilogue.
// grid (64 n x 8 tiles, 2 j-halves); tiles beyond cnt exit immediately.
// mbarrier 3-stage pipeline (R11 winner), A rows gathered via g_gidx.
// ---------------------------------------------------------------------------
#define A_BYTES 16384
#define STAGE_BYTES (2 * A_BYTES)
#define NSTAGE 3
#define SM_DH   0
#define SM_V    1024
#define SM_SRED 2048
#define SM_MBAR 3072
#define SM_STG  4096
#define SM_TOTAL (SM_STG + NSTAGE * STAGE_BYTES)  // 102400

__global__ __launch_bounds__(256, 2) void score_kernel(const float* __restrict__ v) {
    const int n = blockIdx.x >> 3;
    const int tile = blockIdx.x & 7;
    const int row0c = tile * 128;                 // compact row base
    if (row0c >= g_cnt[n]) return;                // inactive tile

    extern __shared__ char smem[];
    const uint32_t sb = smem_u32(smem);
    const int tid = threadIdx.x;
    const int lane = tid & 31;
    const int wid = tid >> 5;
    const int wm = wid & 3;
    const int wn = wid >> 2;
    const int j0 = blockIdx.y * 4;

    // ---- loader precompute (A rows indirect through g_gidx) ----
    uint32_t ldst[4];
    size_t gaoff[4];
    uint32_t gboff_c[4];
#pragma unroll
    for (int t = 0; t < 4; ++t) {
        int u = tid + 256 * t;
        int lrow = u >> 3, lseg = u & 7;
        ldst[t] = (uint32_t)(lrow * 128 + ((lseg ^ (lrow & 7)) << 4));
        int gl = g_gidx[(n << 10) + row0c + lrow];
        gaoff[t] = ((size_t)(n << 10) + gl) * Hh + lseg * 8;
        gboff_c[t] = (uint32_t)(lrow * Hh + lseg * 8);
    }

    // ---- ldsm address bases ----
    uint32_t abase[2], axr[2], bbase[4], bxr[4];
    {
        const int aseg0 = lane >> 4;
        const int bseg0 = (lane >> 3) & 1;
#pragma unroll
        for (int mt = 0; mt < 2; ++mt) {
            int r = wm * 32 + mt * 16 + (lane & 15);
            abase[mt] = (uint32_t)(r * 128 + ((aseg0 ^ (r & 1)) << 4));
            axr[mt] = (uint32_t)(r & 6);
        }
#pragma unroll
        for (int np = 0; np < 4; ++np) {
            int r = wn * 64 + np * 16 + ((lane >> 4) << 3) + (lane & 7);
            bbase[np] = (uint32_t)(r * 128 + ((bseg0 ^ (r & 1)) << 4));
            bxr[np] = (uint32_t)(r & 6);
        }
    }
    const uint32_t ksrot = (uint32_t)(wn << 1);

    auto fill = [&](int cc2) {
        const int s2 = cc2 % NSTAGE;
        const uint32_t base = sb + SM_STG + (uint32_t)s2 * STAGE_BYTES;
        const int kb = (cc2 & 15) * 64;
        const uint32_t jb = (uint32_t)((j0 + (cc2 >> 4)) * 128) * Hh;
#pragma unroll
        for (int t = 0; t < 4; ++t) cp_async16(base + ldst[t], g_Eh + gaoff[t] + kb);
#pragma unroll
        for (int t = 0; t < 4; ++t)
            cp_async16(base + A_BYTES + ldst[t], g_Bh + jb + gboff_c[t] + kb);
        CP_ASYNC_MBAR_ARRIVE_NOINC(sb + SM_MBAR + s2 * 16);
    };

    if (tid == 0) {
#pragma unroll
        for (int s = 0; s < NSTAGE; ++s) {
            MBAR_INIT(sb + SM_MBAR + s * 16, 256);
            MBAR_INIT(sb + SM_MBAR + s * 16 + 8, 256);
        }
    }
    if (tid < 128) {
        int idx = (n << 10) + j0 * 128 + tid;
        ((float*)(smem + SM_DH))[tid] =
            g_dhP[0][idx] + g_dhP[1][idx] + g_dhP[2][idx] + g_dhP[3][idx];
        ((float*)(smem + SM_V))[tid] = v[j0 * 128 + tid];
    }
    __syncthreads();

    float acc[2][8][4];
#pragma unroll
    for (int mt = 0; mt < 2; ++mt)
#pragma unroll
        for (int nt = 0; nt < 8; ++nt)
#pragma unroll
            for (int e = 0; e < 4; ++e) acc[mt][nt][e] = 0.f;

    fill(0);
    fill(1);

    for (int cc = 0; cc < 64; ++cc) {
        const int s = cc % NSTAGE;
        MBAR_WAIT_PARITY(sb + SM_MBAR + s * 16, (cc / 3) & 1);

        const uint32_t base = sb + SM_STG + (uint32_t)s * STAGE_BYTES;
        const uint32_t sA = base;
        const uint32_t sB = base + A_BYTES;

#pragma unroll
        for (int ks = 0; ks < 4; ++ks) {
            const uint32_t ksx = (uint32_t)(((ks + ksrot) & 3) * 2);
            uint32_t ah[2][4];
            ldsm_x4(ah[0], sA + abase[0] + ((ksx ^ axr[0]) << 4));
            ldsm_x4(ah[1], sA + abase[1] + ((ksx ^ axr[1]) << 4));
            uint32_t bb[2][4];
            ldsm_x4(bb[0], sB + bbase[0] + ((ksx ^ bxr[0]) << 4));
#pragma unroll
            for (int np = 0; np < 4; ++np) {
                if (np < 3)
                    ldsm_x4(bb[(np + 1) & 1], sB + bbase[np + 1] + ((ksx ^ bxr[np + 1]) << 4));
                const uint32_t* bq = bb[np & 1];
                mma_f16(acc[0][np * 2 + 0], ah[0], bq[0], bq[1]);
                mma_f16(acc[0][np * 2 + 1], ah[0], bq[2], bq[3]);
                mma_f16(acc[1][np * 2 + 0], ah[1], bq[0], bq[1]);
                mma_f16(acc[1][np * 2 + 1], ah[1], bq[2], bq[3]);
            }
        }
        MBAR_ARRIVE(sb + SM_MBAR + s * 16 + 8);

        const int c2 = cc + 2;
        if (c2 < 64) {
            const int s2 = c2 % NSTAGE;
            if (c2 >= NSTAGE)
                MBAR_WAIT_PARITY(sb + SM_MBAR + s2 * 16 + 8, (c2 / 3 - 1) & 1);
            fill(c2);
        }

        if ((cc & 15) == 15) {
            const int jloc = cc >> 4;
            const int jglob = j0 + jloc;
            const int jb1 = jloc & 1;
            if (jloc < 3 && tid < 128) {
                int idx = (n << 10) + (jglob + 1) * 128 + tid;
                ((float*)(smem + SM_DH + (1 - jb1) * 512))[tid] =
                    g_dhP[0][idx] + g_dhP[1][idx] + g_dhP[2][idx] + g_dhP[3][idx];
                ((float*)(smem + SM_V + (1 - jb1) * 512))[tid] =
                    v[(jglob + 1) * 128 + tid];
            }
            const float* dhs = (const float*)(smem + SM_DH + jb1 * 512);
            const float* vs = (const float*)(smem + SM_V + jb1 * 512);
            float part[4] = {0.f, 0.f, 0.f, 0.f};
#pragma unroll
            for (int mt = 0; mt < 2; ++mt)
#pragma unroll
                for (int nt = 0; nt < 8; ++nt)
#pragma unroll
                    for (int e = 0; e < 4; ++e) {
                        int col = wn * 64 + nt * 8 + (lane & 3) * 2 + (e & 1);
                        part[mt * 2 + (e >> 1)] +=
                            tanh_fast(acc[mt][nt][e] + dhs[col]) * vs[col];
                        acc[mt][nt][e] = 0.f;
                    }
#pragma unroll
            for (int p = 0; p < 4; ++p) {
                part[p] += __shfl_xor_sync(0xffffffffu, part[p], 1);
                part[p] += __shfl_xor_sync(0xffffffffu, part[p], 2);
            }
            float* sred = (float*)(smem + SM_SRED);
            __syncthreads();
            if ((lane & 3) == 0) {
#pragma unroll
                for (int mt = 0; mt < 2; ++mt)
#pragma unroll
                    for (int rr = 0; rr < 2; ++rr) {
                        int row = wm * 32 + mt * 16 + (lane >> 2) + rr * 8;
                        sred[row * 2 + wn] = part[mt * 2 + rr];
                    }
            }
            __syncthreads();
            if (tid < 128)
                g_scorePC[jglob][(n << 10) + row0c + tid] =
                    sred[tid * 2] + sred[tid * 2 + 1];
        }
    }
}

// ---------------------------------------------------------------------------
// Context with inline softmax over COMPACT rows; scatter attn via g_gidx.
// Block (n, lc) handles compact rows [lc*256, lc*256+256).
// ---------------------------------------------------------------------------
__global__ __launch_bounds__(128) void context_kernel(float* __restrict__ attn) {
    __shared__ float sa[256];
    __shared__ int sidx[256];
    __shared__ float red[128];
    const int n = blockIdx.x, lc = blockIdx.y;
    const int tid = threadIdx.x;
    const int cnt = g_cnt[n];

    // softmax over compact rows [0, cnt)
    float s[8];
    float pv[8];
    float lmax = -CUDART_INF_F;
#pragma unroll
    for (int q = 0; q < 8; ++q) {
        int r = tid + 128 * q;
        float a = 0.f;
#pragma unroll
        for (int p = 0; p < 8; ++p) a += g_scorePC[p][(n << 10) + r];
        s[q] = a;
        if (r < cnt) lmax = fmaxf(lmax, a);
    }
    red[tid] = lmax;
    __syncthreads();
    for (int o = 64; o; o >>= 1) {
        if (tid < o) red[tid] = fmaxf(red[tid], red[tid + o]);
        __syncthreads();
    }
    const float mx = red[0];
    __syncthreads();
    float lsum = 0.f;
#pragma unroll
    for (int q = 0; q < 8; ++q) {
        int r = tid + 128 * q;
        pv[q] = (r < cnt) ? __expf(s[q] - mx) : 0.f;
        lsum += pv[q];
    }
    red[tid] = lsum;
    __syncthreads();
    for (int o = 64; o; o >>= 1) {
        if (tid < o) red[tid] += red[tid + o];
        __syncthreads();
    }
    const float inv = 1.0f / red[0];
    __syncthreads();

    // scatter attn + stage our quarter's weights/indices
#pragma unroll
    for (int qq = 0; qq < 2; ++qq) {
        int q = 2 * lc + qq;
        int r = tid + 128 * q;
        int i = tid + 128 * qq;
        if (r < cnt) {
            int l = g_gidx[(n << 10) + r];
            float w = pv[q] * inv;
            attn[(n << 10) + l] = w;
            sa[i] = w;
            sidx[i] = l;
        } else {
            sa[i] = 0.f;
            sidx[i] = 0;
        }
    }
    __syncthreads();

    // context partial over 256 compact rows (gathered E)
    const __half* Ebase = g_Eh + (size_t)(n << 10) * Hh;
    float acc[8] = {};
#pragma unroll 4
    for (int i = 0; i < 256; ++i) {
        float a = sa[i];
        const uint4* rowp = (const uint4*)(Ebase + (size_t)sidx[i] * Hh) + tid;
        uint4 u = *rowp;
        const __half2* h2 = (const __half2*)&u;
#pragma unroll
        for (int q = 0; q < 4; ++q) {
            float2 f = __half22float2(h2[q]);
            acc[q * 2 + 0] += a * f.x;
            acc[q * 2 + 1] += a * f.y;
        }
    }
    float4* dst = &g_ctxP4[lc][n * 256 + tid * 2];
    dst[0] = make_float4(acc[0], acc[1], acc[2], acc[3]);
    dst[1] = make_float4(acc[4], acc[5], acc[6], acc[7]);
}

__global__ __launch_bounds__(256) void ctx_reduce_kernel(float4* __restrict__ ctx4) {
    int i = blockIdx.x * 256 + threadIdx.x;
    float4 a = g_ctxP4[0][i], b = g_ctxP4[1][i], c = g_ctxP4[2][i], d = g_ctxP4[3][i];
    ctx4[i] = make_float4(a.x + b.x + c.x + d.x, a.y + b.y + c.y + d.y,
                          a.z + b.z + c.z + d.z, a.w + b.w + c.w + d.w);
}

// ---------------------------------------------------------------------------
extern "C" void kernel_launch(void* const* d_in, const int* in_sizes, int n_in,
                              void* d_out, int out_size) {
    const float* dec  = (const float*)d_in[0];
    const float* E    = (const float*)d_in[1];
    const int*   mask = (const int*)  d_in[2];
    const float* Wh   = (const float*)d_in[3];
    const float* Ws   = (const float*)d_in[4];
    const float* v    = (const float*)d_in[5];

    float* out  = (float*)d_out;
    float* ctx  = out;
    float* attn = out + Nn * Hh;

    cudaFuncSetAttribute(score_kernel, cudaFuncAttributeMaxDynamicSharedMemorySize, SM_TOTAL);

    bconv_kernel<<<(Hh * Hh / 8) / 256, 256>>>(Ws);
    econv_kernel<<<(Nn * Ll * Hh / 8) / 256, 256>>>(E);
    compact_kernel<<<Nn, 256>>>(mask, attn);
    dh_kernel<<<64, 256>>>(dec, Wh);
    score_kernel<<<dim3(Nn * 8, 2), 256, SM_TOTAL>>>(v);
    context_kernel<<<dim3(Nn, 4), 128>>>(attn);
    ctx_reduce_kernel<<<(Nn * Hh / 4) / 256, 256>>>((float4*)ctx);
}

// round 13
// speedup vs baseline: 1.5262x; 1.0253x over previous
#include <cuda_runtime.h>
#include <cuda_fp16.h>
#include <math_constants.h>
#include <cstdint>

#define Nn 64
#define Ll 1024
#define Hh 1024

// ---------------------------------------------------------------------------
// Device scratch
// ---------------------------------------------------------------------------
__device__ float g_dhP[8][Nn * Hh];
__device__ float g_scorePC[8][Nn * Ll];   // compact-row score partials
__device__ int   g_gidx[Nn * Ll];         // per-n compacted unmasked l indices
__device__ int   g_cnt[Nn];
__device__ __align__(16) __half g_Bh[Hh * Hh];
__device__ __align__(16) __half g_Ehc[Nn * Ll * Hh];  // COMPACT fp16 E
__device__ float4 g_ctxP4[4][Nn * (Hh / 4)];

// ---------------------------------------------------------------------------
// Helpers
// ---------------------------------------------------------------------------
__device__ __forceinline__ uint32_t smem_u32(const void* p) {
    uint32_t a;
    asm("{ .reg .u64 t; cvta.to.shared.u64 t, %1; cvt.u32.u64 %0, t; }" : "=r"(a) : "l"(p));
    return a;
}
__device__ __forceinline__ float tanh_fast(float x) {
    float e = __expf(2.0f * x);
    return 1.0f - __fdividef(2.0f, e + 1.0f);
}
__device__ __forceinline__ void ldsm_x4(uint32_t* r, uint32_t addr) {
    asm volatile("ldmatrix.sync.aligned.m8n8.x4.shared.b16 {%0,%1,%2,%3}, [%4];"
                 : "=r"(r[0]), "=r"(r[1]), "=r"(r[2]), "=r"(r[3]) : "r"(addr));
}
__device__ __forceinline__ void mma_f16(float* c, const uint32_t* a, uint32_t b0, uint32_t b1) {
    asm volatile("mma.sync.aligned.m16n8k16.row.col.f32.f16.f16.f32 "
                 "{%0,%1,%2,%3}, {%4,%5,%6,%7}, {%8,%9}, {%0,%1,%2,%3};"
                 : "+f"(c[0]), "+f"(c[1]), "+f"(c[2]), "+f"(c[3])
                 : "r"(a[0]), "r"(a[1]), "r"(a[2]), "r"(a[3]), "r"(b0), "r"(b1));
}
__device__ __forceinline__ void cp_async16(uint32_t dst, const void* src) {
    asm volatile("cp.async.cg.shared.global [%0], [%1], 16;" :: "r"(dst), "l"(src) : "memory");
}

// ---- mbarrier ops (generic PTX) ----
#define MBAR_INIT(addr, cnt) \
    asm volatile("mbarrier.init.shared.b64 [%0], %1;" :: "r"((uint32_t)(addr)), "r"((uint32_t)(cnt)) : "memory")
#define MBAR_ARRIVE(addr) \
    asm volatile("{\n\t.reg .b64 t;\n\tmbarrier.arrive.shared.b64 t, [%0];\n\t}" \
                 :: "r"((uint32_t)(addr)) : "memory")
#define CP_ASYNC_MBAR_ARRIVE_NOINC(addr) \
    asm volatile("cp.async.mbarrier.arrive.noinc.shared.b64 [%0];" :: "r"((uint32_t)(addr)) : "memory")
#define MBAR_WAIT_PARITY(addr, parity) do {                                              \
    uint32_t _mbar = (uint32_t)(addr);                                                   \
    uint32_t _par  = (uint32_t)(parity);                                                 \
    uint32_t _done;                                                                      \
    asm volatile("{\n\t.reg .pred p;\n\t"                                                \
        "mbarrier.try_wait.parity.acquire.cta.shared::cta.b64 p, [%1], %2;\n\t"          \
        "selp.b32 %0, 1, 0, p;\n\t}" : "=r"(_done) : "r"(_mbar), "r"(_par) : "memory");  \
    if (!_done) {                                                                        \
        asm volatile("{\n\t.reg .pred P1;\n\t"                                           \
            "WL_%=:\n\t"                                                                 \
            "mbarrier.try_wait.parity.acquire.cta.shared::cta.b64 P1, [%0], %1, 0x989680;\n\t" \
            "@P1 bra.uni WD_%=;\n\t"                                                     \
            "bra.uni WL_%=;\n\t"                                                         \
            "WD_%=:\n\t}" :: "r"(_mbar), "r"(_par) : "memory");                          \
    }                                                                                    \
} while (0)

// ---------------------------------------------------------------------------
// Convert Ws -> fp16
// ---------------------------------------------------------------------------
__global__ __launch_bounds__(256) void bconv_kernel(const float* __restrict__ Ws) {
    size_t i = (size_t)blockIdx.x * 256 + threadIdx.x;
    float4 w0 = ((const float4*)Ws)[2 * i];
    float4 w1 = ((const float4*)Ws)[2 * i + 1];
    __half2 h[4];
    h[0] = __floats2half2_rn(w0.x, w0.y);
    h[1] = __floats2half2_rn(w0.z, w0.w);
    h[2] = __floats2half2_rn(w1.x, w1.y);
    h[3] = __floats2half2_rn(w1.z, w1.w);
    ((uint4*)g_Bh)[i] = *(uint4*)h;
}

// ---------------------------------------------------------------------------
// Compact kernel: per n, ordered unmasked l list; zero attn; counts.
// ---------------------------------------------------------------------------
__global__ __launch_bounds__(256) void compact_kernel(const int* __restrict__ mask,
                                                      float* __restrict__ attn) {
    __shared__ int sc[256];
    const int n = blockIdx.x;
    const int tid = threadIdx.x;
    int m[4];
    int c = 0;
#pragma unroll
    for (int q = 0; q < 4; ++q) {
        m[q] = mask[(n << 10) + tid * 4 + q];
        if (!m[q]) ++c;
        attn[(n << 10) + tid * 4 + q] = 0.f;
    }
    sc[tid] = c;
    __syncthreads();
    for (int off = 1; off < 256; off <<= 1) {
        int vv = (tid >= off) ? sc[tid - off] : 0;
        __syncthreads();
        sc[tid] += vv;
        __syncthreads();
    }
    int base = sc[tid] - c;
    if (tid == 255) g_cnt[n] = sc[255];
#pragma unroll
    for (int q = 0; q < 4; ++q)
        if (!m[q]) g_gidx[(n << 10) + base++] = tid * 4 + q;
}

// ---------------------------------------------------------------------------
// Convert E (unmasked rows only) -> COMPACT fp16 layout.
// grid (64 n, 8 tiles of 128 compact rows).
// ---------------------------------------------------------------------------
__global__ __launch_bounds__(256) void econvc_kernel(const float* __restrict__ E) {
    const int n = blockIdx.x;
    const int row0 = blockIdx.y * 128;
    const int cnt = g_cnt[n];
    if (row0 >= cnt) return;
    const int tid = threadIdx.x;
    const int lim = min(128, cnt - row0);
    // tasks: lim rows x 128 uint4 outputs per row
    for (int i = tid; i < 128 * 128; i += 256) {
        int r = i >> 7;
        if (r >= lim) break;
        int u = i & 127;  // uint4 index within row (16B fp16 = 8 cols)
        int gl = g_gidx[(n << 10) + row0 + r];
        const float4* src = (const float4*)(E + ((size_t)(n << 10) + gl) * Hh) + u * 2;
        float4 w0 = src[0], w1 = src[1];
        __half2 h[4];
        h[0] = __floats2half2_rn(w0.x, w0.y);
        h[1] = __floats2half2_rn(w0.z, w0.w);
        h[2] = __floats2half2_rn(w1.x, w1.y);
        h[3] = __floats2half2_rn(w1.z, w1.w);
        ((uint4*)(g_Ehc + ((size_t)(n << 10) + row0 + r) * Hh))[u] = *(uint4*)h;
    }
}

// ---------------------------------------------------------------------------
// dh partials: tiled GEMM, Wh read once. grid 128 = 16 k-blocks x 8 h-splits.
// ---------------------------------------------------------------------------
__global__ __launch_bounds__(256) void dh_kernel(const float* __restrict__ dec,
                                                 const float* __restrict__ Wh) {
    __shared__ float ds[64][68];
    __shared__ float ws[64][68];
    const int tid = threadIdx.x;
    const int kb = (blockIdx.x & 15) * 64;
    const int hs = blockIdx.x >> 4;          // 0..7
    const int n0 = (tid & 15) * 4;
    const int k0 = (tid >> 4) * 4;
    float acc[4][4] = {};
    for (int cc = 0; cc < 2; ++cc) {
        const int hb = hs * 128 + cc * 64;
        __syncthreads();
#pragma unroll
        for (int q = 0; q < 4; ++q) {
            int f4 = tid + 256 * q;
            int r = f4 >> 4;
            int col = f4 & 15;
            float4 a = *(const float4*)(dec + (size_t)r * Hh + hb + col * 4);
            ds[col * 4 + 0][r] = a.x; ds[col * 4 + 1][r] = a.y;
            ds[col * 4 + 2][r] = a.z; ds[col * 4 + 3][r] = a.w;
            float4 b = *(const float4*)(Wh + (size_t)(kb + r) * Hh + hb + col * 4);
            ws[col * 4 + 0][r] = b.x; ws[col * 4 + 1][r] = b.y;
            ws[col * 4 + 2][r] = b.z; ws[col * 4 + 3][r] = b.w;
        }
        __syncthreads();
#pragma unroll 8
        for (int h = 0; h < 64; ++h) {
            float a[4], b[4];
            *(float4*)a = *(const float4*)&ds[h][n0];
            *(float4*)b = *(const float4*)&ws[h][k0];
#pragma unroll
            for (int i = 0; i < 4; ++i)
#pragma unroll
                for (int j = 0; j < 4; ++j) acc[i][j] += a[i] * b[j];
        }
    }
#pragma unroll
    for (int i = 0; i < 4; ++i)
#pragma unroll
        for (int j = 0; j < 4; ++j)
            g_dhP[hs][(n0 + i) * Hh + kb + k0 + j] = acc[i][j];
}

__device__ __forceinline__ float dh_sum(int idx) {
    float a = 0.f;
#pragma unroll
    for (int p = 0; p < 8; ++p) a += g_dhP[p][idx];
    return a;
}

// ---------------------------------------------------------------------------
// Fused score kernel on COMPACT rows (regular addressing into g_Ehc).
// grid (64 n x 8 tiles, 2 j-halves); tiles beyond cnt exit immediately.
// mbarrier 3-stage pipeline.
// ---------------------------------------------------------------------------
#define A_BYTES 16384
#define STAGE_BYTES (2 * A_BYTES)
#define NSTAGE 3
#define SM_DH   0
#define SM_V    1024
#define SM_SRED 2048
#define SM_MBAR 3072
#define SM_STG  4096
#define SM_TOTAL (SM_STG + NSTAGE * STAGE_BYTES)  // 102400

__global__ __launch_bounds__(256, 2) void score_kernel(const float* __restrict__ v) {
    const int n = blockIdx.x >> 3;
    const int tile = blockIdx.x & 7;
    const int row0c = tile * 128;
    if (row0c >= g_cnt[n]) return;

    extern __shared__ char smem[];
    const uint32_t sb = smem_u32(smem);
    const int tid = threadIdx.x;
    const int lane = tid & 31;
    const int wid = tid >> 5;
    const int wm = wid & 3;
    const int wn = wid >> 2;
    const int j0 = blockIdx.y * 4;

    // ---- loader precompute (regular compact addressing) ----
    uint32_t ldst[4];
    size_t gaoff[4];
    uint32_t gboff_c[4];
#pragma unroll
    for (int t = 0; t < 4; ++t) {
        int u = tid + 256 * t;
        int lrow = u >> 3, lseg = u & 7;
        ldst[t] = (uint32_t)(lrow * 128 + ((lseg ^ (lrow & 7)) << 4));
        gaoff[t] = ((size_t)((n << 10) + row0c + lrow)) * Hh + lseg * 8;
        gboff_c[t] = (uint32_t)(lrow * Hh + lseg * 8);
    }

    // ---- ldsm address bases ----
    uint32_t abase[2], axr[2], bbase[4], bxr[4];
    {
        const int aseg0 = lane >> 4;
        const int bseg0 = (lane >> 3) & 1;
#pragma unroll
        for (int mt = 0; mt < 2; ++mt) {
            int r = wm * 32 + mt * 16 + (lane & 15);
            abase[mt] = (uint32_t)(r * 128 + ((aseg0 ^ (r & 1)) << 4));
            axr[mt] = (uint32_t)(r & 6);
        }
#pragma unroll
        for (int np = 0; np < 4; ++np) {
            int r = wn * 64 + np * 16 + ((lane >> 4) << 3) + (lane & 7);
            bbase[np] = (uint32_t)(r * 128 + ((bseg0 ^ (r & 1)) << 4));
            bxr[np] = (uint32_t)(r & 6);
        }
    }
    const uint32_t ksrot = (uint32_t)(wn << 1);

    auto fill = [&](int cc2) {
        const int s2 = cc2 % NSTAGE;
        const uint32_t base = sb + SM_STG + (uint32_t)s2 * STAGE_BYTES;
        const int kb = (cc2 & 15) * 64;
        const uint32_t jb = (uint32_t)((j0 + (cc2 >> 4)) * 128) * Hh;
#pragma unroll
        for (int t = 0; t < 4; ++t) cp_async16(base + ldst[t], g_Ehc + gaoff[t] + kb);
#pragma unroll
        for (int t = 0; t < 4; ++t)
            cp_async16(base + A_BYTES + ldst[t], g_Bh + jb + gboff_c[t] + kb);
        CP_ASYNC_MBAR_ARRIVE_NOINC(sb + SM_MBAR + s2 * 16);
    };

    if (tid == 0) {
#pragma unroll
        for (int s = 0; s < NSTAGE; ++s) {
            MBAR_INIT(sb + SM_MBAR + s * 16, 256);
            MBAR_INIT(sb + SM_MBAR + s * 16 + 8, 256);
        }
    }
    if (tid < 128) {
        ((float*)(smem + SM_DH))[tid] = dh_sum((n << 10) + j0 * 128 + tid);
        ((float*)(smem + SM_V))[tid] = v[j0 * 128 + tid];
    }
    __syncthreads();

    float acc[2][8][4];
#pragma unroll
    for (int mt = 0; mt < 2; ++mt)
#pragma unroll
        for (int nt = 0; nt < 8; ++nt)
#pragma unroll
            for (int e = 0; e < 4; ++e) acc[mt][nt][e] = 0.f;

    fill(0);
    fill(1);

    for (int cc = 0; cc < 64; ++cc) {
        const int s = cc % NSTAGE;
        MBAR_WAIT_PARITY(sb + SM_MBAR + s * 16, (cc / 3) & 1);

        const uint32_t base = sb + SM_STG + (uint32_t)s * STAGE_BYTES;
        const uint32_t sA = base;
        const uint32_t sB = base + A_BYTES;

#pragma unroll
        for (int ks = 0; ks < 4; ++ks) {
            const uint32_t ksx = (uint32_t)(((ks + ksrot) & 3) * 2);
            uint32_t ah[2][4];
            ldsm_x4(ah[0], sA + abase[0] + ((ksx ^ axr[0]) << 4));
            ldsm_x4(ah[1], sA + abase[1] + ((ksx ^ axr[1]) << 4));
            uint32_t bb[2][4];
            ldsm_x4(bb[0], sB + bbase[0] + ((ksx ^ bxr[0]) << 4));
#pragma unroll
            for (int np = 0; np < 4; ++np) {
                if (np < 3)
                    ldsm_x4(bb[(np + 1) & 1], sB + bbase[np + 1] + ((ksx ^ bxr[np + 1]) << 4));
                const uint32_t* bq = bb[np & 1];
                mma_f16(acc[0][np * 2 + 0], ah[0], bq[0], bq[1]);
                mma_f16(acc[0][np * 2 + 1], ah[0], bq[2], bq[3]);
                mma_f16(acc[1][np * 2 + 0], ah[1], bq[0], bq[1]);
                mma_f16(acc[1][np * 2 + 1], ah[1], bq[2], bq[3]);
            }
        }
        MBAR_ARRIVE(sb + SM_MBAR + s * 16 + 8);

        const int c2 = cc + 2;
        if (c2 < 64) {
            const int s2 = c2 % NSTAGE;
            if (c2 >= NSTAGE)
                MBAR_WAIT_PARITY(sb + SM_MBAR + s2 * 16 + 8, (c2 / 3 - 1) & 1);
            fill(c2);
        }

        if ((cc & 15) == 15) {
            const int jloc = cc >> 4;
            const int jglob = j0 + jloc;
            const int jb1 = jloc & 1;
            if (jloc < 3 && tid < 128) {
                ((float*)(smem + SM_DH + (1 - jb1) * 512))[tid] =
                    dh_sum((n << 10) + (jglob + 1) * 128 + tid);
                ((float*)(smem + SM_V + (1 - jb1) * 512))[tid] =
                    v[(jglob + 1) * 128 + tid];
            }
            const float* dhs = (const float*)(smem + SM_DH + jb1 * 512);
            const float* vs = (const float*)(smem + SM_V + jb1 * 512);
            float part[4] = {0.f, 0.f, 0.f, 0.f};
#pragma unroll
            for (int mt = 0; mt < 2; ++mt)
#pragma unroll
                for (int nt = 0; nt < 8; ++nt)
#pragma unroll
                    for (int e = 0; e < 4; ++e) {
                        int col = wn * 64 + nt * 8 + (lane & 3) * 2 + (e & 1);
                        part[mt * 2 + (e >> 1)] +=
                            tanh_fast(acc[mt][nt][e] + dhs[col]) * vs[col];
                        acc[mt][nt][e] = 0.f;
                    }
#pragma unroll
            for (int p = 0; p < 4; ++p) {
                part[p] += __shfl_xor_sync(0xffffffffu, part[p], 1);
                part[p] += __shfl_xor_sync(0xffffffffu, part[p], 2);
            }
            float* sred = (float*)(smem + SM_SRED);
            __syncthreads();
            if ((lane & 3) == 0) {
#pragma unroll
                for (int mt = 0; mt < 2; ++mt)
#pragma unroll
                    for (int rr = 0; rr < 2; ++rr) {
                        int row = wm * 32 + mt * 16 + (lane >> 2) + rr * 8;
                        sred[row * 2 + wn] = part[mt * 2 + rr];
                    }
            }
            __syncthreads();
            if (tid < 128)
                g_scorePC[jglob][(n << 10) + row0c + tid] =
                    sred[tid * 2] + sred[tid * 2 + 1];
        }
    }
}

// ---------------------------------------------------------------------------
// Context with inline softmax over COMPACT rows; E reads sequential.
// Block (n, lc): compact rows [lc*256, lc*256+lim).
// ---------------------------------------------------------------------------
__global__ __launch_bounds__(128) void context_kernel(float* __restrict__ attn) {
    __shared__ float sa[256];
    __shared__ float red[128];
    const int n = blockIdx.x, lc = blockIdx.y;
    const int tid = threadIdx.x;
    const int cnt = g_cnt[n];

    float s[8];
    float pv[8];
    float lmax = -CUDART_INF_F;
#pragma unroll
    for (int q = 0; q < 8; ++q) {
        int r = tid + 128 * q;
        float a = 0.f;
#pragma unroll
        for (int p = 0; p < 8; ++p) a += g_scorePC[p][(n << 10) + r];
        s[q] = a;
        if (r < cnt) lmax = fmaxf(lmax, a);
    }
    red[tid] = lmax;
    __syncthreads();
    for (int o = 64; o; o >>= 1) {
        if (tid < o) red[tid] = fmaxf(red[tid], red[tid + o]);
        __syncthreads();
    }
    const float mx = red[0];
    __syncthreads();
    float lsum = 0.f;
#pragma unroll
    for (int q = 0; q < 8; ++q) {
        int r = tid + 128 * q;
        pv[q] = (r < cnt) ? __expf(s[q] - mx) : 0.f;
        lsum += pv[q];
    }
    red[tid] = lsum;
    __syncthreads();
    for (int o = 64; o; o >>= 1) {
        if (tid < o) red[tid] += red[tid + o];
        __syncthreads();
    }
    const float inv = 1.0f / red[0];
    __syncthreads();

    // scatter attn + stage our quarter's weights
#pragma unroll
    for (int qq = 0; qq < 2; ++qq) {
        int q = 2 * lc + qq;
        int r = tid + 128 * q;
        int i = tid + 128 * qq;
        float w = 0.f;
        if (r < cnt) {
            int l = g_gidx[(n << 10) + r];
            w = pv[q] * inv;
            attn[(n << 10) + l] = w;
        }
        sa[i] = w;
    }
    __syncthreads();

    // context partial: sequential compact E rows, bounded by cnt
    const int lim = min(256, cnt - lc * 256);  // may be <=0 (handled by loop)
    const uint4* Ep = (const uint4*)(g_Ehc + (size_t)((n << 10) + lc * 256) * Hh) + tid;
    float acc[8] = {};
#pragma unroll 4
    for (int i = 0; i < lim; ++i) {
        uint4 u = Ep[(size_t)i * 128];
        const __half2* h2 = (const __half2*)&u;
        float a = sa[i];
#pragma unroll
        for (int q = 0; q < 4; ++q) {
            float2 f = __half22float2(h2[q]);
            acc[q * 2 + 0] += a * f.x;
            acc[q * 2 + 1] += a * f.y;
        }
    }
    float4* dst = &g_ctxP4[lc][n * 256 + tid * 2];
    dst[0] = make_float4(acc[0], acc[1], acc[2], acc[3]);
    dst[1] = make_float4(acc[4], acc[5], acc[6], acc[7]);
}

__global__ __launch_bounds__(256) void ctx_reduce_kernel(float4* __restrict__ ctx4) {
    int i = blockIdx.x * 256 + threadIdx.x;
    float4 a = g_ctxP4[0][i], b = g_ctxP4[1][i], c = g_ctxP4[2][i], d = g_ctxP4[3][i];
    ctx4[i] = make_float4(a.x + b.x + c.x + d.x, a.y + b.y + c.y + d.y,
                          a.z + b.z + c.z + d.z, a.w + b.w + c.w + d.w);
}

// ---------------------------------------------------------------------------
extern "C" void kernel_launch(void* const* d_in, const int* in_sizes, int n_in,
                              void* d_out, int out_size) {
    const float* dec  = (const float*)d_in[0];
    const float* E    = (const float*)d_in[1];
    const int*   mask = (const int*)  d_in[2];
    const float* Wh   = (const float*)d_in[3];
    const float* Ws   = (const float*)d_in[4];
    const float* v    = (const float*)d_in[5];

    float* out  = (float*)d_out;
    float* ctx  = out;
    float* attn = out + Nn * Hh;

    cudaFuncSetAttribute(score_kernel, cudaFuncAttributeMaxDynamicSharedMemorySize, SM_TOTAL);

    bconv_kernel<<<(Hh * Hh / 8) / 256, 256>>>(Ws);
    compact_kernel<<<Nn, 256>>>(mask, attn);
    econvc_kernel<<<dim3(Nn, 8), 256>>>(E);
    dh_kernel<<<128, 256>>>(dec, Wh);
    score_kernel<<<dim3(Nn * 8, 2), 256, SM_TOTAL>>>(v);
    context_kernel<<<dim3(Nn, 4), 128>>>(attn);
    ctx_reduce_kernel<<<(Nn * Hh / 4) / 256, 256>>>((float4*)ctx);
}